// round 2
// baseline (speedup 1.0000x reference)
#include <cuda_runtime.h>
#include <math.h>

#define IMG 96
#define PSZ 8
#define GD 12
#define CDIM 768
#define NHEAD 8
#define HD 96
#define NPATCH 1728
#define NTOK 1729
#define LDS_ 1732            // padded leading dim for score rows (16B-aligned float4)
#define BQ 2
#define NCLS 3

// ---------------- scratch (device globals; no allocation allowed) ----------------
__device__ float g_pat[(size_t)BQ * NPATCH * 512];
__device__ float g_tmp[(size_t)BQ * NPATCH * CDIM];
__device__ float g_x  [(size_t)BQ * NTOK * CDIM];
__device__ float g_q  [(size_t)BQ * NTOK * CDIM];
__device__ float g_k  [(size_t)BQ * NTOK * CDIM];
__device__ float g_v  [(size_t)BQ * NTOK * CDIM];
__device__ float g_S  [(size_t)BQ * NHEAD * NTOK * LDS_];   // ~192MB scores
__device__ float g_x2 [(size_t)BQ * NTOK * CDIM];
__device__ float g_kv [(size_t)BQ * NTOK * 2 * CDIM];
__device__ float g_q0 [BQ * CDIM];
__device__ float g_oc [BQ * CDIM];
__device__ float g_fin[BQ * CDIM];

// guarded float4 load: p[gk..gk+3], gk % 4 == 0, p 16B-aligned
__device__ __forceinline__ float4 ld4_guard(const float* __restrict__ p, int gk, int K) {
    if (gk + 3 < K) return *(const float4*)(p + gk);
    float4 v = make_float4(0.f, 0.f, 0.f, 0.f);
    if (gk     < K) v.x = p[gk];
    if (gk + 1 < K) v.y = p[gk + 1];
    if (gk + 2 < K) v.z = p[gk + 2];
    return v;
}

// ---------------- 128x128x16 tiled GEMM, 8x8 per-thread, float4 smem reads --------
// TRANS_B=1: C[m,n] = sum_k A[m,k]*B[n,k]
// TRANS_B=0: C[m,n] = sum_k A[m,k]*B[k,n]
template <int TRANS_B>
__global__ void __launch_bounds__(256)
gemm_k(const float* __restrict__ A, const float* __restrict__ Bm,
       const float* __restrict__ bias, float* __restrict__ Cm,
       int M, int Nn, int K, int lda, int ldb, int ldc,
       size_t sAb, size_t sAh, size_t sBb, size_t sBh,
       size_t sCb, size_t sCh, int nh,
       float alphaC, const float* __restrict__ alphaPtr, int accum)
{
    int z = blockIdx.z;
    int bb = z / nh, hh = z % nh;
    A  += (size_t)bb * sAb + (size_t)hh * sAh;
    Bm += (size_t)bb * sBb + (size_t)hh * sBh;
    Cm += (size_t)bb * sCb + (size_t)hh * sCh;

    __shared__ float As[16][132];
    __shared__ float Bs[16][132];

    int tid = threadIdx.x;
    int tx = tid & 15, ty = tid >> 4;
    int m0 = blockIdx.y * 128, n0 = blockIdx.x * 128;

    // A/B (transposed-store) loader indices: 64 rows x (4 k-quads)
    int ar = tid >> 2;            // 0..63
    int ak = (tid & 3) * 4;       // 0,4,8,12
    // NN B loader indices: 8 k-rows x 32 col-quads
    int bk = tid >> 5;            // 0..7
    int bc = (tid & 31) * 4;      // 0..124

    float acc[8][8] = {};

    for (int k0 = 0; k0 < K; k0 += 16) {
        // ---- load A tile (store k-major) ----
#pragma unroll
        for (int h = 0; h < 2; h++) {
            int r = ar + h * 64;
            int gm = m0 + r;
            float4 va = make_float4(0.f, 0.f, 0.f, 0.f);
            if (gm < M) va = ld4_guard(A + (size_t)gm * lda, k0 + ak, K);
            As[ak + 0][r] = va.x; As[ak + 1][r] = va.y;
            As[ak + 2][r] = va.z; As[ak + 3][r] = va.w;
        }
        // ---- load B tile ----
        if (TRANS_B) {
#pragma unroll
            for (int h = 0; h < 2; h++) {
                int r = ar + h * 64;
                int gn = n0 + r;
                float4 vb = make_float4(0.f, 0.f, 0.f, 0.f);
                if (gn < Nn) vb = ld4_guard(Bm + (size_t)gn * ldb, k0 + ak, K);
                Bs[ak + 0][r] = vb.x; Bs[ak + 1][r] = vb.y;
                Bs[ak + 2][r] = vb.z; Bs[ak + 3][r] = vb.w;
            }
        } else {
#pragma unroll
            for (int h = 0; h < 2; h++) {
                int kk = bk + h * 8;
                int gk = k0 + kk;
                int gn = n0 + bc;
                float4 vb = make_float4(0.f, 0.f, 0.f, 0.f);
                if (gk < K) {
                    const float* rowp = Bm + (size_t)gk * ldb;
                    if (gn + 3 < Nn) vb = *(const float4*)(rowp + gn);
                    else {
                        if (gn     < Nn) vb.x = rowp[gn];
                        if (gn + 1 < Nn) vb.y = rowp[gn + 1];
                        if (gn + 2 < Nn) vb.z = rowp[gn + 2];
                    }
                }
                *(float4*)&Bs[kk][bc] = vb;
            }
        }
        __syncthreads();

        // ---- compute ----
#pragma unroll
        for (int kk = 0; kk < 16; kk++) {
            float4 a0 = *(const float4*)&As[kk][ty * 4];
            float4 a1 = *(const float4*)&As[kk][ty * 4 + 64];
            float4 b0 = *(const float4*)&Bs[kk][tx * 4];
            float4 b1 = *(const float4*)&Bs[kk][tx * 4 + 64];
            float a[8] = {a0.x, a0.y, a0.z, a0.w, a1.x, a1.y, a1.z, a1.w};
            float b[8] = {b0.x, b0.y, b0.z, b0.w, b1.x, b1.y, b1.z, b1.w};
#pragma unroll
            for (int i = 0; i < 8; i++)
#pragma unroll
                for (int j = 0; j < 8; j++)
                    acc[i][j] += a[i] * b[j];
        }
        __syncthreads();
    }

    float alpha = alphaC * (alphaPtr ? *alphaPtr : 1.f);
#pragma unroll
    for (int i = 0; i < 8; i++) {
        int gm = m0 + ty * 4 + (i & 3) + ((i >> 2) ? 64 : 0);
        if (gm >= M) continue;
#pragma unroll
        for (int j = 0; j < 8; j++) {
            int gn = n0 + tx * 4 + (j & 3) + ((j >> 2) ? 64 : 0);
            if (gn >= Nn) continue;
            float v = acc[i][j];
            if (bias) v += bias[gn];
            v *= alpha;
            size_t off = (size_t)gm * ldc + gn;
            if (accum) v += Cm[off];
            Cm[off] = v;
        }
    }
}

// ---------------- im2col patch gather (float4) ----------------
__global__ void gather_k(const float* __restrict__ smri, float* __restrict__ pat) {
    int idx = blockIdx.x * 256 + threadIdx.x;          // float4 index
    if (idx >= BQ * NPATCH * 512 / 4) return;
    int e  = idx * 4;
    int kk = e & 511;
    int m  = e >> 9;
    int bb = m / NPATCH, p = m % NPATCH;
    int gx = p / (GD * GD), gy = (p / GD) % GD, gz = p % GD;
    int i = kk >> 6, j = (kk >> 3) & 7, kq = kk & 7;
    const float* src = smri + (((size_t)bb * IMG + gx * PSZ + i) * IMG + gy * PSZ + j) * IMG
                       + gz * PSZ + kq;
    *(float4*)(pat + e) = *(const float4*)src;
}

// ---------------- LN(patch embed) + cls + pos_embed ----------------
__global__ void ln_pos_k(const float* __restrict__ tmp, const float* __restrict__ g,
                         const float* __restrict__ b, const float* __restrict__ cls,
                         const float* __restrict__ pos, float* __restrict__ x)
{
    int bt = blockIdx.x;
    int bb = bt / NTOK, t = bt % NTOK;
    int tid = threadIdx.x;
    float* out = x + (size_t)bt * CDIM;
    const float* pp = pos + (size_t)t * CDIM;
    if (t == 0) {
        for (int c = tid; c < CDIM; c += 256) out[c] = cls[c] + pp[c];
        return;
    }
    const float* row = tmp + ((size_t)bb * NPATCH + (t - 1)) * CDIM;
    __shared__ float red[256];
    float s = 0.f, s2 = 0.f;
    for (int c = tid; c < CDIM; c += 256) { float v = row[c]; s += v; s2 += v * v; }
    red[tid] = s; __syncthreads();
    for (int st = 128; st > 0; st >>= 1) { if (tid < st) red[tid] += red[tid + st]; __syncthreads(); }
    float mean = red[0] / CDIM; __syncthreads();
    red[tid] = s2; __syncthreads();
    for (int st = 128; st > 0; st >>= 1) { if (tid < st) red[tid] += red[tid + st]; __syncthreads(); }
    float var = red[0] / CDIM - mean * mean;
    float inv = rsqrtf(var + 1e-5f);
    for (int c = tid; c < CDIM; c += 256)
        out[c] = (row[c] - mean) * inv * g[c] + b[c] + pp[c];
}

// ---------------- row softmax (region bias softmax-invariant); zero 3 pad cols ----
__global__ void softmax_rows(float* __restrict__ S) {
    __shared__ float buf[NTOK];
    __shared__ float red[256];
    size_t row = blockIdx.x;
    float* p = S + row * (size_t)LDS_;
    int tid = threadIdx.x;
    float mx = -1e30f;
    for (int i = tid; i < NTOK; i += 256) { float v = p[i]; buf[i] = v; mx = fmaxf(mx, v); }
    red[tid] = mx; __syncthreads();
    for (int st = 128; st > 0; st >>= 1) { if (tid < st) red[tid] = fmaxf(red[tid], red[tid + st]); __syncthreads(); }
    mx = red[0]; __syncthreads();
    float sm = 0.f;
    for (int i = tid; i < NTOK; i += 256) { float e = __expf(buf[i] - mx); buf[i] = e; sm += e; }
    red[tid] = sm; __syncthreads();
    for (int st = 128; st > 0; st >>= 1) { if (tid < st) red[tid] += red[tid + st]; __syncthreads(); }
    float inv = 1.f / red[0];
    for (int i = tid; i < NTOK; i += 256) p[i] = buf[i] * inv;
    if (tid < LDS_ - NTOK) p[NTOK + tid] = 0.f;       // zero pad columns
}

// ---------------- CLS-query attention for a branch ----------------
__global__ void cls_attn_k(const float* __restrict__ q0, const float* __restrict__ kv,
                           float* __restrict__ oc)
{
    int z = blockIdx.x;
    int bb = z / NHEAD, hh = z % NHEAD;
    __shared__ float sS[NTOK];
    __shared__ float sq[HD];
    __shared__ float red[128];
    int tid = threadIdx.x;
    for (int j = tid; j < HD; j += 128) sq[j] = q0[bb * CDIM + hh * HD + j];
    __syncthreads();
    const float scale = 0.10206207261596577f;
    float mx = -1e30f;
    for (int t = tid; t < NTOK; t += 128) {
        const float* kr = kv + ((size_t)(bb * NTOK + t)) * (2 * CDIM) + hh * HD;
        float s = 0.f;
        for (int j = 0; j < HD; j++) s += sq[j] * kr[j];
        s *= scale;
        sS[t] = s;
        mx = fmaxf(mx, s);
    }
    red[tid] = mx; __syncthreads();
    for (int st = 64; st > 0; st >>= 1) { if (tid < st) red[tid] = fmaxf(red[tid], red[tid + st]); __syncthreads(); }
    mx = red[0]; __syncthreads();
    float sm = 0.f;
    for (int t = tid; t < NTOK; t += 128) { float e = __expf(sS[t] - mx); sS[t] = e; sm += e; }
    red[tid] = sm; __syncthreads();
    for (int st = 64; st > 0; st >>= 1) { if (tid < st) red[tid] += red[tid + st]; __syncthreads(); }
    float inv = 1.f / red[0];
    __syncthreads();
    if (tid < HD) {
        float acc = 0.f;
        for (int t = 0; t < NTOK; t++)
            acc += sS[t] * kv[((size_t)(bb * NTOK + t)) * (2 * CDIM) + CDIM + hh * HD + tid];
        oc[bb * CDIM + hh * HD + tid] = acc * inv;
    }
}

// ---------------- LN + head on CLS ----------------
__global__ void head_k(const float* __restrict__ fin, const float* __restrict__ g,
                       const float* __restrict__ b, const float* __restrict__ hw,
                       const float* __restrict__ hb, float* __restrict__ out)
{
    int bb = blockIdx.x;
    const float* row = fin + bb * CDIM;
    __shared__ float red[256];
    __shared__ float sn[CDIM];
    int tid = threadIdx.x;
    float s = 0.f, s2 = 0.f;
    for (int c = tid; c < CDIM; c += 256) { float v = row[c]; s += v; s2 += v * v; }
    red[tid] = s; __syncthreads();
    for (int st = 128; st > 0; st >>= 1) { if (tid < st) red[tid] += red[tid + st]; __syncthreads(); }
    float mean = red[0] / CDIM; __syncthreads();
    red[tid] = s2; __syncthreads();
    for (int st = 128; st > 0; st >>= 1) { if (tid < st) red[tid] += red[tid + st]; __syncthreads(); }
    float var = red[0] / CDIM - mean * mean;
    float inv = rsqrtf(var + 1e-5f);
    for (int c = tid; c < CDIM; c += 256) sn[c] = (row[c] - mean) * inv * g[c] + b[c];
    __syncthreads();
    if (tid < NCLS) {
        float acc = hb[tid];
        for (int c = 0; c < CDIM; c++) acc += sn[c] * hw[tid * CDIM + c];
        out[bb * NCLS + tid] = acc;
    }
}

// ---------------- host ----------------
static inline int cdiv(int a, int b) { return (a + b - 1) / b; }

static void gemm_nt(const float* A, const float* B, const float* bias, float* C,
                    int M, int Nn, int K, int lda, int ldb, int ldc,
                    size_t sAb = 0, size_t sAh = 0, size_t sBb = 0, size_t sBh = 0,
                    size_t sCb = 0, size_t sCh = 0, int nh = 1, int batches = 1,
                    float alphaC = 1.f, const float* alphaPtr = nullptr, int accum = 0)
{
    dim3 grid(cdiv(Nn, 128), cdiv(M, 128), batches);
    gemm_k<1><<<grid, 256>>>(A, B, bias, C, M, Nn, K, lda, ldb, ldc,
                             sAb, sAh, sBb, sBh, sCb, sCh, nh, alphaC, alphaPtr, accum);
}

static void gemm_nn(const float* A, const float* B, const float* bias, float* C,
                    int M, int Nn, int K, int lda, int ldb, int ldc,
                    size_t sAb, size_t sAh, size_t sBb, size_t sBh,
                    size_t sCb, size_t sCh, int nh, int batches)
{
    dim3 grid(cdiv(Nn, 128), cdiv(M, 128), batches);
    gemm_k<0><<<grid, 256>>>(A, B, bias, C, M, Nn, K, lda, ldb, ldc,
                             sAb, sAh, sBb, sBh, sCb, sCh, nh, 1.f, nullptr, 0);
}

extern "C" void kernel_launch(void* const* d_in, const int* in_sizes, int n_in,
                              void* d_out, int out_size)
{
    const float* smri     = (const float*)d_in[0];
    const float* conv_w   = (const float*)d_in[2];
    const float* conv_b   = (const float*)d_in[3];
    const float* pe_ln_g  = (const float*)d_in[4];
    const float* pe_ln_b  = (const float*)d_in[5];
    const float* q_w      = (const float*)d_in[6];
    const float* q_b      = (const float*)d_in[7];
    const float* k_w      = (const float*)d_in[8];
    const float* k_b      = (const float*)d_in[9];
    const float* v_w      = (const float*)d_in[10];
    const float* v_b      = (const float*)d_in[11];
    const float* loc_in_w = (const float*)d_in[13];
    const float* loc_in_b = (const float*)d_in[14];
    const float* loc_out_w= (const float*)d_in[15];
    const float* loc_out_b= (const float*)d_in[16];
    const float* glob_in_w = (const float*)d_in[17];
    const float* glob_in_b = (const float*)d_in[18];
    const float* glob_out_w= (const float*)d_in[19];
    const float* glob_out_b= (const float*)d_in[20];
    const float* w_local  = (const float*)d_in[21];
    const float* w_global = (const float*)d_in[22];
    const float* cls_tok  = (const float*)d_in[23];
    const float* pos_emb  = (const float*)d_in[24];
    const float* head_ln_g= (const float*)d_in[25];
    const float* head_ln_b= (const float*)d_in[26];
    const float* head_w   = (const float*)d_in[27];
    const float* head_b   = (const float*)d_in[28];
    float* out = (float*)d_out;

    float *pat, *tmp, *x, *q, *k, *v, *S, *x2, *kv, *q0, *oc, *fin;
    cudaGetSymbolAddress((void**)&pat, g_pat);
    cudaGetSymbolAddress((void**)&tmp, g_tmp);
    cudaGetSymbolAddress((void**)&x,   g_x);
    cudaGetSymbolAddress((void**)&q,   g_q);
    cudaGetSymbolAddress((void**)&k,   g_k);
    cudaGetSymbolAddress((void**)&v,   g_v);
    cudaGetSymbolAddress((void**)&S,   g_S);
    cudaGetSymbolAddress((void**)&x2,  g_x2);
    cudaGetSymbolAddress((void**)&kv,  g_kv);
    cudaGetSymbolAddress((void**)&q0,  g_q0);
    cudaGetSymbolAddress((void**)&oc,  g_oc);
    cudaGetSymbolAddress((void**)&fin, g_fin);

    const float scale = 0.10206207261596577f;   // 1/sqrt(96)
    const size_t sT = (size_t)NTOK * CDIM;
    const size_t sSh = (size_t)NTOK * LDS_;
    const size_t sSb = (size_t)NHEAD * sSh;

    // 1) patch im2col + embed GEMM
    gather_k<<<cdiv(BQ * NPATCH * 512 / 4, 256), 256>>>(smri, pat);
    gemm_nt(pat, conv_w, conv_b, tmp, BQ * NPATCH, CDIM, 512, 512, 512, CDIM);

    // 2) LN + cls + pos
    ln_pos_k<<<BQ * NTOK, 256>>>(tmp, pe_ln_g, pe_ln_b, cls_tok, pos_emb, x);

    // 3) regional QKV projections
    gemm_nt(x, q_w, q_b, q, BQ * NTOK, CDIM, CDIM, CDIM, CDIM, CDIM);
    gemm_nt(x, k_w, k_b, k, BQ * NTOK, CDIM, CDIM, CDIM, CDIM, CDIM);
    gemm_nt(x, v_w, v_b, v, BQ * NTOK, CDIM, CDIM, CDIM, CDIM, CDIM);

    // 4) scores = scale * Q K^T  (region bias dropped: softmax-invariant)
    gemm_nt(q, k, nullptr, S, NTOK, NTOK, HD, CDIM, CDIM, LDS_,
            sT, HD, sT, HD, sSb, sSh, NHEAD, BQ * NHEAD, scale);

    // 5) softmax rows (+ zero pad cols)
    softmax_rows<<<BQ * NHEAD * NTOK, 256>>>(S);

    // 6) x2 = A @ V
    gemm_nn(S, v, nullptr, x2, NTOK, HD, NTOK, LDS_, CDIM, CDIM,
            sSb, sSh, sT, HD, sT, HD, NHEAD, BQ * NHEAD);

    // 7) branches: only CLS row matters downstream
    gemm_nt(x2, loc_in_w + (size_t)CDIM * CDIM, loc_in_b + CDIM, kv,
            BQ * NTOK, 2 * CDIM, CDIM, CDIM, CDIM, 2 * CDIM);
    gemm_nt(x2, loc_in_w, loc_in_b, q0, BQ, CDIM, CDIM, (int)sT, CDIM, CDIM);
    cls_attn_k<<<BQ * NHEAD, 128>>>(q0, kv, oc);
    gemm_nt(oc, loc_out_w, loc_out_b, fin, BQ, CDIM, CDIM, CDIM, CDIM, CDIM,
            0, 0, 0, 0, 0, 0, 1, 1, 1.f, w_local, 0);
    gemm_nt(x2, glob_in_w + (size_t)CDIM * CDIM, glob_in_b + CDIM, kv,
            BQ * NTOK, 2 * CDIM, CDIM, CDIM, CDIM, 2 * CDIM);
    gemm_nt(x2, glob_in_w, glob_in_b, q0, BQ, CDIM, CDIM, (int)sT, CDIM, CDIM);
    cls_attn_k<<<BQ * NHEAD, 128>>>(q0, kv, oc);
    gemm_nt(oc, glob_out_w, glob_out_b, fin, BQ, CDIM, CDIM, CDIM, CDIM, CDIM,
            0, 0, 0, 0, 0, 0, 1, 1, 1.f, w_global, 1);

    // 8) head on CLS
    head_k<<<BQ, 256>>>(fin, head_ln_g, head_ln_b, head_w, head_b, out);
}

// round 4
// speedup vs baseline: 1.2858x; 1.2858x over previous
#include <cuda_runtime.h>
#include <math.h>

#define IMG 96
#define PSZ 8
#define GD 12
#define CDIM 768
#define NHEAD 8
#define HD 96
#define NPATCH 1728
#define NTOK 1729
#define LDS_ 1744            // padded score ld: multiple of 16 for whole k-tiles
#define BQ 2
#define NCLS 3

// ---------------- scratch (device globals) ----------------
__device__ float g_pat [(size_t)BQ * NPATCH * 512];
__device__ float g_tmp [(size_t)BQ * NPATCH * CDIM];
__device__ float g_x   [(size_t)BQ * NTOK * CDIM];
__device__ float g_wqkv[(size_t)3 * CDIM * CDIM];
__device__ float g_bqkv[3 * CDIM];
__device__ float g_qkv [(size_t)BQ * NTOK * 3 * CDIM];
__device__ float g_S   [(size_t)BQ * NHEAD * NTOK * LDS_];   // ~193MB
__device__ float g_x2  [(size_t)BQ * NTOK * CDIM];
__device__ float g_kv  [(size_t)BQ * NTOK * 2 * CDIM];
__device__ float g_q0  [BQ * CDIM];
__device__ float g_oc  [BQ * CDIM];
__device__ float g_fin [BQ * CDIM];

__device__ __forceinline__ float4 ld4_guard(const float* __restrict__ p, int gk, int K) {
    if (gk + 3 < K) return *(const float4*)(p + gk);
    float4 v = make_float4(0.f, 0.f, 0.f, 0.f);
    if (gk     < K) v.x = p[gk];
    if (gk + 1 < K) v.y = p[gk + 1];
    if (gk + 2 < K) v.z = p[gk + 2];
    return v;
}

// ------------- 128x128x16 double-buffered GEMM, 8x8/thread, float4 smem ----------
// TRANS_B=1: C[m,n] = sum_k A[m,k]*B[n,k]   TRANS_B=0: C[m,n] = sum_k A[m,k]*B[k,n]
template <int TRANS_B>
__global__ void __launch_bounds__(256, 2)
gemm_k(const float* __restrict__ A, const float* __restrict__ Bm,
       const float* __restrict__ bias, float* __restrict__ Cm,
       int M, int Nn, int K, int lda, int ldb, int ldc,
       size_t sAb, size_t sAh, size_t sBb, size_t sBh,
       size_t sCb, size_t sCh, int nh,
       float alphaC, const float* __restrict__ alphaPtr, int accum)
{
    int z = blockIdx.z;
    int bb = z / nh, hh = z % nh;
    A  += (size_t)bb * sAb + (size_t)hh * sAh;
    Bm += (size_t)bb * sBb + (size_t)hh * sBh;
    Cm += (size_t)bb * sCb + (size_t)hh * sCh;

    __shared__ float As[2][16][132];
    __shared__ float Bs[2][16][132];

    int tid = threadIdx.x;
    int tx = tid & 15, ty = tid >> 4;
    int m0 = blockIdx.y * 128, n0 = blockIdx.x * 128;

    int ar = tid >> 2;            // 0..63
    int ak = (tid & 3) * 4;       // 0,4,8,12
    int bk = tid >> 5;            // 0..7  (NN loader)
    int bc = (tid & 31) * 4;      // 0..124

    float acc[8][8] = {};
    float4 pa[2], pb[2];

    int ktiles = (K + 15) / 16;

    // prologue: load tile 0
    {
        int k0 = 0;
#pragma unroll
        for (int h = 0; h < 2; h++) {
            int gm = m0 + ar + h * 64;
            pa[h] = (gm < M) ? ld4_guard(A + (size_t)gm * lda, k0 + ak, K)
                             : make_float4(0.f, 0.f, 0.f, 0.f);
        }
        if (TRANS_B) {
#pragma unroll
            for (int h = 0; h < 2; h++) {
                int gn = n0 + ar + h * 64;
                pb[h] = (gn < Nn) ? ld4_guard(Bm + (size_t)gn * ldb, k0 + ak, K)
                                  : make_float4(0.f, 0.f, 0.f, 0.f);
            }
        } else {
#pragma unroll
            for (int h = 0; h < 2; h++) {
                int gk = k0 + bk + h * 8;
                int gn = n0 + bc;
                float4 v = make_float4(0.f, 0.f, 0.f, 0.f);
                if (gk < K) {
                    const float* rp = Bm + (size_t)gk * ldb;
                    if (gn + 3 < Nn) v = *(const float4*)(rp + gn);
                    else {
                        if (gn     < Nn) v.x = rp[gn];
                        if (gn + 1 < Nn) v.y = rp[gn + 1];
                        if (gn + 2 < Nn) v.z = rp[gn + 2];
                    }
                }
                pb[h] = v;
            }
        }
        // store into buffer 0
#pragma unroll
        for (int h = 0; h < 2; h++) {
            int r = ar + h * 64;
            As[0][ak + 0][r] = pa[h].x; As[0][ak + 1][r] = pa[h].y;
            As[0][ak + 2][r] = pa[h].z; As[0][ak + 3][r] = pa[h].w;
        }
        if (TRANS_B) {
#pragma unroll
            for (int h = 0; h < 2; h++) {
                int r = ar + h * 64;
                Bs[0][ak + 0][r] = pb[h].x; Bs[0][ak + 1][r] = pb[h].y;
                Bs[0][ak + 2][r] = pb[h].z; Bs[0][ak + 3][r] = pb[h].w;
            }
        } else {
#pragma unroll
            for (int h = 0; h < 2; h++)
                *(float4*)&Bs[0][bk + h * 8][bc] = pb[h];
        }
    }
    __syncthreads();

    for (int t = 0; t < ktiles; t++) {
        int cur = t & 1;
        // prefetch tile t+1 into regs
        if (t + 1 < ktiles) {
            int k0 = (t + 1) * 16;
#pragma unroll
            for (int h = 0; h < 2; h++) {
                int gm = m0 + ar + h * 64;
                pa[h] = (gm < M) ? ld4_guard(A + (size_t)gm * lda, k0 + ak, K)
                                 : make_float4(0.f, 0.f, 0.f, 0.f);
            }
            if (TRANS_B) {
#pragma unroll
                for (int h = 0; h < 2; h++) {
                    int gn = n0 + ar + h * 64;
                    pb[h] = (gn < Nn) ? ld4_guard(Bm + (size_t)gn * ldb, k0 + ak, K)
                                      : make_float4(0.f, 0.f, 0.f, 0.f);
                }
            } else {
#pragma unroll
                for (int h = 0; h < 2; h++) {
                    int gk = k0 + bk + h * 8;
                    int gn = n0 + bc;
                    float4 v = make_float4(0.f, 0.f, 0.f, 0.f);
                    if (gk < K) {
                        const float* rp = Bm + (size_t)gk * ldb;
                        if (gn + 3 < Nn) v = *(const float4*)(rp + gn);
                        else {
                            if (gn     < Nn) v.x = rp[gn];
                            if (gn + 1 < Nn) v.y = rp[gn + 1];
                            if (gn + 2 < Nn) v.z = rp[gn + 2];
                        }
                    }
                    pb[h] = v;
                }
            }
        }
        // compute tile t
#pragma unroll
        for (int kk = 0; kk < 16; kk++) {
            float4 a0 = *(const float4*)&As[cur][kk][ty * 4];
            float4 a1 = *(const float4*)&As[cur][kk][ty * 4 + 64];
            float4 b0 = *(const float4*)&Bs[cur][kk][tx * 4];
            float4 b1 = *(const float4*)&Bs[cur][kk][tx * 4 + 64];
            float a[8] = {a0.x, a0.y, a0.z, a0.w, a1.x, a1.y, a1.z, a1.w};
            float b[8] = {b0.x, b0.y, b0.z, b0.w, b1.x, b1.y, b1.z, b1.w};
#pragma unroll
            for (int i = 0; i < 8; i++)
#pragma unroll
                for (int j = 0; j < 8; j++)
                    acc[i][j] += a[i] * b[j];
        }
        // store prefetched regs into other buffer
        if (t + 1 < ktiles) {
            int nxt = cur ^ 1;
#pragma unroll
            for (int h = 0; h < 2; h++) {
                int r = ar + h * 64;
                As[nxt][ak + 0][r] = pa[h].x; As[nxt][ak + 1][r] = pa[h].y;
                As[nxt][ak + 2][r] = pa[h].z; As[nxt][ak + 3][r] = pa[h].w;
            }
            if (TRANS_B) {
#pragma unroll
                for (int h = 0; h < 2; h++) {
                    int r = ar + h * 64;
                    Bs[nxt][ak + 0][r] = pb[h].x; Bs[nxt][ak + 1][r] = pb[h].y;
                    Bs[nxt][ak + 2][r] = pb[h].z; Bs[nxt][ak + 3][r] = pb[h].w;
                }
            } else {
#pragma unroll
                for (int h = 0; h < 2; h++)
                    *(float4*)&Bs[nxt][bk + h * 8][bc] = pb[h];
            }
            __syncthreads();
        }
    }

    float alpha = alphaC * (alphaPtr ? *alphaPtr : 1.f);
#pragma unroll
    for (int i = 0; i < 8; i++) {
        int gm = m0 + ty * 4 + (i & 3) + ((i >> 2) ? 64 : 0);
        if (gm >= M) continue;
#pragma unroll
        for (int j = 0; j < 8; j++) {
            int gn = n0 + tx * 4 + (j & 3) + ((j >> 2) ? 64 : 0);
            if (gn >= Nn) continue;
            float v = acc[i][j];
            if (bias) v += bias[gn];
            v *= alpha;
            size_t off = (size_t)gm * ldc + gn;
            if (accum) v += Cm[off];
            Cm[off] = v;
        }
    }
}

// ---------------- pack QKV weights/bias into one matrix ----------------
__global__ void pack_qkv_k(const float* __restrict__ qw, const float* __restrict__ kw,
                           const float* __restrict__ vw, const float* __restrict__ qb,
                           const float* __restrict__ kb, const float* __restrict__ vb,
                           float* __restrict__ w, float* __restrict__ bias)
{
    int idx = blockIdx.x * 256 + threadIdx.x;                 // float4 index
    int tot = 3 * CDIM * CDIM / 4;
    if (idx < tot) {
        int e = idx * 4;
        int which = e / (CDIM * CDIM);
        int off = e - which * (CDIM * CDIM);
        const float* src = which == 0 ? qw : which == 1 ? kw : vw;
        *(float4*)(w + e) = *(const float4*)(src + off);
    }
    if (idx < 3 * CDIM) {
        int which = idx / CDIM, off = idx % CDIM;
        bias[idx] = (which == 0 ? qb : which == 1 ? kb : vb)[off];
    }
}

// ---------------- im2col patch gather (float4) ----------------
__global__ void gather_k(const float* __restrict__ smri, float* __restrict__ pat) {
    int idx = blockIdx.x * 256 + threadIdx.x;
    if (idx >= BQ * NPATCH * 512 / 4) return;
    int e  = idx * 4;
    int kk = e & 511;
    int m  = e >> 9;
    int bb = m / NPATCH, p = m % NPATCH;
    int gx = p / (GD * GD), gy = (p / GD) % GD, gz = p % GD;
    int i = kk >> 6, j = (kk >> 3) & 7, kq = kk & 7;
    const float* src = smri + (((size_t)bb * IMG + gx * PSZ + i) * IMG + gy * PSZ + j) * IMG
                       + gz * PSZ + kq;
    *(float4*)(pat + e) = *(const float4*)src;
}

// ---------------- LN(patch embed) + cls + pos_embed ----------------
__global__ void ln_pos_k(const float* __restrict__ tmp, const float* __restrict__ g,
                         const float* __restrict__ b, const float* __restrict__ cls,
                         const float* __restrict__ pos, float* __restrict__ x)
{
    int bt = blockIdx.x;
    int bb = bt / NTOK, t = bt % NTOK;
    int tid = threadIdx.x;
    float* out = x + (size_t)bt * CDIM;
    const float* pp = pos + (size_t)t * CDIM;
    if (t == 0) {
        for (int c = tid; c < CDIM; c += 256) out[c] = cls[c] + pp[c];
        return;
    }
    const float* row = tmp + ((size_t)bb * NPATCH + (t - 1)) * CDIM;
    __shared__ float red[256];
    float s = 0.f, s2 = 0.f;
    for (int c = tid; c < CDIM; c += 256) { float v = row[c]; s += v; s2 += v * v; }
    red[tid] = s; __syncthreads();
    for (int st = 128; st > 0; st >>= 1) { if (tid < st) red[tid] += red[tid + st]; __syncthreads(); }
    float mean = red[0] / CDIM; __syncthreads();
    red[tid] = s2; __syncthreads();
    for (int st = 128; st > 0; st >>= 1) { if (tid < st) red[tid] += red[tid + st]; __syncthreads(); }
    float var = red[0] / CDIM - mean * mean;
    float inv = rsqrtf(var + 1e-5f);
    for (int c = tid; c < CDIM; c += 256)
        out[c] = (row[c] - mean) * inv * g[c] + b[c] + pp[c];
}

// ---------------- row softmax; zero pad cols ----------------
__global__ void softmax_rows(float* __restrict__ S) {
    __shared__ float buf[NTOK];
    __shared__ float red[256];
    size_t row = blockIdx.x;
    float* p = S + row * (size_t)LDS_;
    int tid = threadIdx.x;
    float mx = -1e30f;
    for (int i = tid; i < NTOK; i += 256) { float v = p[i]; buf[i] = v; mx = fmaxf(mx, v); }
    red[tid] = mx; __syncthreads();
    for (int st = 128; st > 0; st >>= 1) { if (tid < st) red[tid] = fmaxf(red[tid], red[tid + st]); __syncthreads(); }
    mx = red[0]; __syncthreads();
    float sm = 0.f;
    for (int i = tid; i < NTOK; i += 256) { float e = __expf(buf[i] - mx); buf[i] = e; sm += e; }
    red[tid] = sm; __syncthreads();
    for (int st = 128; st > 0; st >>= 1) { if (tid < st) red[tid] += red[tid + st]; __syncthreads(); }
    float inv = 1.f / red[0];
    for (int i = tid; i < NTOK; i += 256) p[i] = buf[i] * inv;
    if (tid < LDS_ - NTOK) p[NTOK + tid] = 0.f;
}

// ---------------- CLS-query attention for a branch ----------------
__global__ void cls_attn_k(const float* __restrict__ q0, const float* __restrict__ kv,
                           float* __restrict__ oc)
{
    int z = blockIdx.x;
    int bb = z / NHEAD, hh = z % NHEAD;
    __shared__ float sS[NTOK];
    __shared__ float sq[HD];
    __shared__ float red[128];
    int tid = threadIdx.x;
    for (int j = tid; j < HD; j += 128) sq[j] = q0[bb * CDIM + hh * HD + j];
    __syncthreads();
    const float scale = 0.10206207261596577f;
    float mx = -1e30f;
    for (int t = tid; t < NTOK; t += 128) {
        const float* kr = kv + ((size_t)(bb * NTOK + t)) * (2 * CDIM) + hh * HD;
        float s = 0.f;
        for (int j = 0; j < HD; j++) s += sq[j] * kr[j];
        s *= scale;
        sS[t] = s;
        mx = fmaxf(mx, s);
    }
    red[tid] = mx; __syncthreads();
    for (int st = 64; st > 0; st >>= 1) { if (tid < st) red[tid] = fmaxf(red[tid], red[tid + st]); __syncthreads(); }
    mx = red[0]; __syncthreads();
    float sm = 0.f;
    for (int t = tid; t < NTOK; t += 128) { float e = __expf(sS[t] - mx); sS[t] = e; sm += e; }
    red[tid] = sm; __syncthreads();
    for (int st = 64; st > 0; st >>= 1) { if (tid < st) red[tid] += red[tid + st]; __syncthreads(); }
    float inv = 1.f / red[0];
    __syncthreads();
    if (tid < HD) {
        float acc = 0.f;
        for (int t = 0; t < NTOK; t++)
            acc += sS[t] * kv[((size_t)(bb * NTOK + t)) * (2 * CDIM) + CDIM + hh * HD + tid];
        oc[bb * CDIM + hh * HD + tid] = acc * inv;
    }
}

// ---------------- LN + head on CLS ----------------
__global__ void head_k(const float* __restrict__ fin, const float* __restrict__ g,
                       const float* __restrict__ b, const float* __restrict__ hw,
                       const float* __restrict__ hb, float* __restrict__ out)
{
    int bb = blockIdx.x;
    const float* row = fin + bb * CDIM;
    __shared__ float red[256];
    __shared__ float sn[CDIM];
    int tid = threadIdx.x;
    float s = 0.f, s2 = 0.f;
    for (int c = tid; c < CDIM; c += 256) { float v = row[c]; s += v; s2 += v * v; }
    red[tid] = s; __syncthreads();
    for (int st = 128; st > 0; st >>= 1) { if (tid < st) red[tid] += red[tid + st]; __syncthreads(); }
    float mean = red[0] / CDIM; __syncthreads();
    red[tid] = s2; __syncthreads();
    for (int st = 128; st > 0; st >>= 1) { if (tid < st) red[tid] += red[tid + st]; __syncthreads(); }
    float var = red[0] / CDIM - mean * mean;
    float inv = rsqrtf(var + 1e-5f);
    for (int c = tid; c < CDIM; c += 256) sn[c] = (row[c] - mean) * inv * g[c] + b[c];
    __syncthreads();
    if (tid < NCLS) {
        float acc = hb[tid];
        for (int c = 0; c < CDIM; c++) acc += sn[c] * hw[tid * CDIM + c];
        out[bb * NCLS + tid] = acc;
    }
}

// ---------------- host ----------------
static inline int cdiv(int a, int b) { return (a + b - 1) / b; }

static void gemm_nt(const float* A, const float* B, const float* bias, float* C,
                    int M, int Nn, int K, int lda, int ldb, int ldc,
                    size_t sAb = 0, size_t sAh = 0, size_t sBb = 0, size_t sBh = 0,
                    size_t sCb = 0, size_t sCh = 0, int nh = 1, int batches = 1,
                    float alphaC = 1.f, const float* alphaPtr = nullptr, int accum = 0)
{
    dim3 grid(cdiv(Nn, 128), cdiv(M, 128), batches);
    gemm_k<1><<<grid, 256>>>(A, B, bias, C, M, Nn, K, lda, ldb, ldc,
                             sAb, sAh, sBb, sBh, sCb, sCh, nh, alphaC, alphaPtr, accum);
}

static void gemm_nn(const float* A, const float* B, const float* bias, float* C,
                    int M, int Nn, int K, int lda, int ldb, int ldc,
                    size_t sAb, size_t sAh, size_t sBb, size_t sBh,
                    size_t sCb, size_t sCh, int nh, int batches)
{
    dim3 grid(cdiv(Nn, 128), cdiv(M, 128), batches);
    gemm_k<0><<<grid, 256>>>(A, B, bias, C, M, Nn, K, lda, ldb, ldc,
                             sAb, sAh, sBb, sBh, sCb, sCh, nh, 1.f, nullptr, 0);
}

extern "C" void kernel_launch(void* const* d_in, const int* in_sizes, int n_in,
                              void* d_out, int out_size)
{
    const float* smri     = (const float*)d_in[0];
    const float* conv_w   = (const float*)d_in[2];
    const float* conv_b   = (const float*)d_in[3];
    const float* pe_ln_g  = (const float*)d_in[4];
    const float* pe_ln_b  = (const float*)d_in[5];
    const float* q_w      = (const float*)d_in[6];
    const float* q_b      = (const float*)d_in[7];
    const float* k_w      = (const float*)d_in[8];
    const float* k_b      = (const float*)d_in[9];
    const float* v_w      = (const float*)d_in[10];
    const float* v_b      = (const float*)d_in[11];
    const float* loc_in_w = (const float*)d_in[13];
    const float* loc_in_b = (const float*)d_in[14];
    const float* loc_out_w= (const float*)d_in[15];
    const float* loc_out_b= (const float*)d_in[16];
    const float* glob_in_w = (const float*)d_in[17];
    const float* glob_in_b = (const float*)d_in[18];
    const float* glob_out_w= (const float*)d_in[19];
    const float* glob_out_b= (const float*)d_in[20];
    const float* w_local  = (const float*)d_in[21];
    const float* w_global = (const float*)d_in[22];
    const float* cls_tok  = (const float*)d_in[23];
    const float* pos_emb  = (const float*)d_in[24];
    const float* head_ln_g= (const float*)d_in[25];
    const float* head_ln_b= (const float*)d_in[26];
    const float* head_w   = (const float*)d_in[27];
    const float* head_b   = (const float*)d_in[28];
    float* out = (float*)d_out;

    float *pat, *tmp, *x, *wqkv, *bqkv, *qkv, *S, *x2, *kv, *q0, *oc, *fin;
    cudaGetSymbolAddress((void**)&pat,  g_pat);
    cudaGetSymbolAddress((void**)&tmp,  g_tmp);
    cudaGetSymbolAddress((void**)&x,    g_x);
    cudaGetSymbolAddress((void**)&wqkv, g_wqkv);
    cudaGetSymbolAddress((void**)&bqkv, g_bqkv);
    cudaGetSymbolAddress((void**)&qkv,  g_qkv);
    cudaGetSymbolAddress((void**)&S,    g_S);
    cudaGetSymbolAddress((void**)&x2,   g_x2);
    cudaGetSymbolAddress((void**)&kv,   g_kv);
    cudaGetSymbolAddress((void**)&q0,   g_q0);
    cudaGetSymbolAddress((void**)&oc,   g_oc);
    cudaGetSymbolAddress((void**)&fin,  g_fin);

    const float scale = 0.10206207261596577f;   // 1/sqrt(96)
    const size_t sT  = (size_t)NTOK * CDIM;
    const size_t sT3 = (size_t)NTOK * 3 * CDIM;
    const size_t sSh = (size_t)NTOK * LDS_;
    const size_t sSb = (size_t)NHEAD * sSh;

    // 0) pack QKV weights
    pack_qkv_k<<<cdiv(3 * CDIM * CDIM / 4, 256), 256>>>(q_w, k_w, v_w, q_b, k_b, v_b,
                                                        wqkv, bqkv);

    // 1) patch im2col + embed GEMM
    gather_k<<<cdiv(BQ * NPATCH * 512 / 4, 256), 256>>>(smri, pat);
    gemm_nt(pat, conv_w, conv_b, tmp, BQ * NPATCH, CDIM, 512, 512, 512, CDIM);

    // 2) LN + cls + pos
    ln_pos_k<<<BQ * NTOK, 256>>>(tmp, pe_ln_g, pe_ln_b, cls_tok, pos_emb, x);

    // 3) fused QKV projection: qkv[b,t, 0:C|C:2C|2C:3C] = q|k|v
    gemm_nt(x, wqkv, bqkv, qkv, BQ * NTOK, 3 * CDIM, CDIM, CDIM, CDIM, 3 * CDIM);

    // 4) scores = scale * Q K^T   (region bias is softmax-invariant -> dropped)
    gemm_nt(qkv, qkv + CDIM, nullptr, S, NTOK, NTOK, HD, 3 * CDIM, 3 * CDIM, LDS_,
            sT3, HD, sT3, HD, sSb, sSh, NHEAD, BQ * NHEAD, scale);

    // 5) softmax rows (+ zero pad cols)
    softmax_rows<<<BQ * NHEAD * NTOK, 256>>>(S);

    // 6) x2 = A @ V     (K = LDS_ whole tiles; pad cols are zero)
    gemm_nn(S, qkv + 2 * CDIM, nullptr, x2, NTOK, HD, LDS_, LDS_, 3 * CDIM, CDIM,
            sSb, sSh, sT3, HD, sT, HD, NHEAD, BQ * NHEAD);

    // 7) branches (only CLS row used downstream)
    gemm_nt(x2, loc_in_w + (size_t)CDIM * CDIM, loc_in_b + CDIM, kv,
            BQ * NTOK, 2 * CDIM, CDIM, CDIM, CDIM, 2 * CDIM);
    gemm_nt(x2, loc_in_w, loc_in_b, q0, BQ, CDIM, CDIM, (int)sT, CDIM, CDIM);
    cls_attn_k<<<BQ * NHEAD, 128>>>(q0, kv, oc);
    gemm_nt(oc, loc_out_w, loc_out_b, fin, BQ, CDIM, CDIM, CDIM, CDIM, CDIM,
            0, 0, 0, 0, 0, 0, 1, 1, 1.f, w_local, 0);
    gemm_nt(x2, glob_in_w + (size_t)CDIM * CDIM, glob_in_b + CDIM, kv,
            BQ * NTOK, 2 * CDIM, CDIM, CDIM, CDIM, 2 * CDIM);
    gemm_nt(x2, glob_in_w, glob_in_b, q0, BQ, CDIM, CDIM, (int)sT, CDIM, CDIM);
    cls_attn_k<<<BQ * NHEAD, 128>>>(q0, kv, oc);
    gemm_nt(oc, glob_out_w, glob_out_b, fin, BQ, CDIM, CDIM, CDIM, CDIM, CDIM,
            0, 0, 0, 0, 0, 0, 1, 1, 1.f, w_global, 1);

    // 8) head on CLS
    head_k<<<BQ, 256>>>(fin, head_ln_g, head_ln_b, head_w, head_b, out);
}

// round 5
// speedup vs baseline: 1.3884x; 1.0798x over previous
#include <cuda_runtime.h>
#include <math.h>

#define IMG 96
#define PSZ 8
#define GD 12
#define CDIM 768
#define NHEAD 8
#define HD 96
#define NPATCH 1728
#define NTOK 1729
#define LDS_ 1744            // padded score ld: multiple of 16 for whole k-tiles
#define BQ 2
#define NCLS 3

typedef unsigned long long ull;

// ---------------- scratch (device globals) ----------------
__device__ float g_pat [(size_t)BQ * NPATCH * 512];
__device__ float g_tmp [(size_t)BQ * NPATCH * CDIM];
__device__ float g_x   [(size_t)BQ * NTOK * CDIM];
__device__ float g_wqkv[(size_t)3 * CDIM * CDIM];
__device__ float g_bqkv[3 * CDIM];
__device__ float g_qkv [(size_t)BQ * NTOK * 3 * CDIM];
__device__ float g_S   [(size_t)BQ * NHEAD * NTOK * LDS_];   // ~193MB
__device__ float g_x2  [(size_t)BQ * NTOK * CDIM];
__device__ float g_kv  [(size_t)BQ * NTOK * 2 * CDIM];
__device__ float g_q0  [BQ * CDIM];
__device__ float g_oc  [BQ * CDIM];
__device__ float g_fin [BQ * CDIM];

__device__ __forceinline__ float4 ld4_guard(const float* __restrict__ p, int gk, int K) {
    if (gk + 3 < K) return *(const float4*)(p + gk);
    float4 v = make_float4(0.f, 0.f, 0.f, 0.f);
    if (gk     < K) v.x = p[gk];
    if (gk + 1 < K) v.y = p[gk + 1];
    if (gk + 2 < K) v.z = p[gk + 2];
    return v;
}

// ------------- 128x128x16 double-buffered GEMM, 8x8/thread, FFMA2 packed math ----
// TRANS_B=1: C[m,n] = sum_k A[m,k]*B[n,k]   TRANS_B=0: C[m,n] = sum_k A[m,k]*B[k,n]
template <int TRANS_B>
__global__ void __launch_bounds__(256, 2)
gemm_k(const float* __restrict__ A, const float* __restrict__ Bm,
       const float* __restrict__ bias, float* __restrict__ Cm,
       int M, int Nn, int K, int lda, int ldb, int ldc,
       size_t sAb, size_t sAh, size_t sBb, size_t sBh,
       size_t sCb, size_t sCh, int nh,
       float alphaC, const float* __restrict__ alphaPtr, int accum)
{
    int z = blockIdx.z;
    int bb = z / nh, hh = z % nh;
    A  += (size_t)bb * sAb + (size_t)hh * sAh;
    Bm += (size_t)bb * sBb + (size_t)hh * sBh;
    Cm += (size_t)bb * sCb + (size_t)hh * sCh;

    __shared__ float As[2][16][132];
    __shared__ float Bs[2][16][132];

    int tid = threadIdx.x;
    int tx = tid & 15, ty = tid >> 4;
    int m0 = blockIdx.y * 128, n0 = blockIdx.x * 128;

    int ar = tid >> 2;            // 0..63
    int ak = (tid & 3) * 4;       // 0,4,8,12
    int bk = tid >> 5;            // 0..7  (NN loader)
    int bc = (tid & 31) * 4;      // 0..124

    // packed accumulators: acc2[i][jp] = cols (pair) for row i
    ull acc2[8][4];
#pragma unroll
    for (int i = 0; i < 8; i++)
#pragma unroll
        for (int j = 0; j < 4; j++) acc2[i][j] = 0ULL;

    float4 pa[2], pb[2];
    int ktiles = (K + 15) / 16;

    // prologue: load tile 0
    {
        int k0 = 0;
#pragma unroll
        for (int h = 0; h < 2; h++) {
            int gm = m0 + ar + h * 64;
            pa[h] = (gm < M) ? ld4_guard(A + (size_t)gm * lda, k0 + ak, K)
                             : make_float4(0.f, 0.f, 0.f, 0.f);
        }
        if (TRANS_B) {
#pragma unroll
            for (int h = 0; h < 2; h++) {
                int gn = n0 + ar + h * 64;
                pb[h] = (gn < Nn) ? ld4_guard(Bm + (size_t)gn * ldb, k0 + ak, K)
                                  : make_float4(0.f, 0.f, 0.f, 0.f);
            }
        } else {
#pragma unroll
            for (int h = 0; h < 2; h++) {
                int gk = k0 + bk + h * 8;
                int gn = n0 + bc;
                float4 v = make_float4(0.f, 0.f, 0.f, 0.f);
                if (gk < K) {
                    const float* rp = Bm + (size_t)gk * ldb;
                    if (gn + 3 < Nn) v = *(const float4*)(rp + gn);
                    else {
                        if (gn     < Nn) v.x = rp[gn];
                        if (gn + 1 < Nn) v.y = rp[gn + 1];
                        if (gn + 2 < Nn) v.z = rp[gn + 2];
                    }
                }
                pb[h] = v;
            }
        }
#pragma unroll
        for (int h = 0; h < 2; h++) {
            int r = ar + h * 64;
            As[0][ak + 0][r] = pa[h].x; As[0][ak + 1][r] = pa[h].y;
            As[0][ak + 2][r] = pa[h].z; As[0][ak + 3][r] = pa[h].w;
        }
        if (TRANS_B) {
#pragma unroll
            for (int h = 0; h < 2; h++) {
                int r = ar + h * 64;
                Bs[0][ak + 0][r] = pb[h].x; Bs[0][ak + 1][r] = pb[h].y;
                Bs[0][ak + 2][r] = pb[h].z; Bs[0][ak + 3][r] = pb[h].w;
            }
        } else {
#pragma unroll
            for (int h = 0; h < 2; h++)
                *(float4*)&Bs[0][bk + h * 8][bc] = pb[h];
        }
    }
    __syncthreads();

    for (int t = 0; t < ktiles; t++) {
        int cur = t & 1;
        // prefetch tile t+1 into regs
        if (t + 1 < ktiles) {
            int k0 = (t + 1) * 16;
#pragma unroll
            for (int h = 0; h < 2; h++) {
                int gm = m0 + ar + h * 64;
                pa[h] = (gm < M) ? ld4_guard(A + (size_t)gm * lda, k0 + ak, K)
                                 : make_float4(0.f, 0.f, 0.f, 0.f);
            }
            if (TRANS_B) {
#pragma unroll
                for (int h = 0; h < 2; h++) {
                    int gn = n0 + ar + h * 64;
                    pb[h] = (gn < Nn) ? ld4_guard(Bm + (size_t)gn * ldb, k0 + ak, K)
                                      : make_float4(0.f, 0.f, 0.f, 0.f);
                }
            } else {
#pragma unroll
                for (int h = 0; h < 2; h++) {
                    int gk = k0 + bk + h * 8;
                    int gn = n0 + bc;
                    float4 v = make_float4(0.f, 0.f, 0.f, 0.f);
                    if (gk < K) {
                        const float* rp = Bm + (size_t)gk * ldb;
                        if (gn + 3 < Nn) v = *(const float4*)(rp + gn);
                        else {
                            if (gn     < Nn) v.x = rp[gn];
                            if (gn + 1 < Nn) v.y = rp[gn + 1];
                            if (gn + 2 < Nn) v.z = rp[gn + 2];
                        }
                    }
                    pb[h] = v;
                }
            }
        }
        // ---- compute tile t with packed FFMA2 ----
#pragma unroll
        for (int kk = 0; kk < 16; kk++) {
            float4 a0 = *(const float4*)&As[cur][kk][ty * 4];
            float4 a1 = *(const float4*)&As[cur][kk][ty * 4 + 64];
            ulonglong2 bq0 = *(const ulonglong2*)&Bs[cur][kk][tx * 4];
            ulonglong2 bq1 = *(const ulonglong2*)&Bs[cur][kk][tx * 4 + 64];
            ull bp[4] = {bq0.x, bq0.y, bq1.x, bq1.y};
            float a[8] = {a0.x, a0.y, a0.z, a0.w, a1.x, a1.y, a1.z, a1.w};
#pragma unroll
            for (int i = 0; i < 8; i++) {
                ull ai;
                asm("mov.b64 %0, {%1, %1};" : "=l"(ai) : "f"(a[i]));
#pragma unroll
                for (int jp = 0; jp < 4; jp++)
                    asm("fma.rn.f32x2 %0, %1, %2, %0;"
                        : "+l"(acc2[i][jp]) : "l"(ai), "l"(bp[jp]));
            }
        }
        // store prefetched regs into other buffer
        if (t + 1 < ktiles) {
            int nxt = cur ^ 1;
#pragma unroll
            for (int h = 0; h < 2; h++) {
                int r = ar + h * 64;
                As[nxt][ak + 0][r] = pa[h].x; As[nxt][ak + 1][r] = pa[h].y;
                As[nxt][ak + 2][r] = pa[h].z; As[nxt][ak + 3][r] = pa[h].w;
            }
            if (TRANS_B) {
#pragma unroll
                for (int h = 0; h < 2; h++) {
                    int r = ar + h * 64;
                    Bs[nxt][ak + 0][r] = pb[h].x; Bs[nxt][ak + 1][r] = pb[h].y;
                    Bs[nxt][ak + 2][r] = pb[h].z; Bs[nxt][ak + 3][r] = pb[h].w;
                }
            } else {
#pragma unroll
                for (int h = 0; h < 2; h++)
                    *(float4*)&Bs[nxt][bk + h * 8][bc] = pb[h];
            }
            __syncthreads();
        }
    }

    float alpha = alphaC * (alphaPtr ? *alphaPtr : 1.f);
#pragma unroll
    for (int i = 0; i < 8; i++) {
        int gm = m0 + ty * 4 + (i & 3) + ((i >> 2) ? 64 : 0);
        if (gm >= M) continue;
#pragma unroll
        for (int jp = 0; jp < 4; jp++) {
            float lo, hi;
            asm("mov.b64 {%0, %1}, %2;" : "=f"(lo), "=f"(hi) : "l"(acc2[i][jp]));
            int col0 = n0 + tx * 4 + (jp & 1) * 2 + ((jp >> 1) ? 64 : 0);
#pragma unroll
            for (int u = 0; u < 2; u++) {
                int gn = col0 + u;
                if (gn >= Nn) continue;
                float v = u ? hi : lo;
                if (bias) v += bias[gn];
                v *= alpha;
                size_t off = (size_t)gm * ldc + gn;
                if (accum) v += Cm[off];
                Cm[off] = v;
            }
        }
    }
}

// ---------------- pack QKV weights/bias into one matrix ----------------
__global__ void pack_qkv_k(const float* __restrict__ qw, const float* __restrict__ kw,
                           const float* __restrict__ vw, const float* __restrict__ qb,
                           const float* __restrict__ kb, const float* __restrict__ vb,
                           float* __restrict__ w, float* __restrict__ bias)
{
    int idx = blockIdx.x * 256 + threadIdx.x;
    int tot = 3 * CDIM * CDIM / 4;
    if (idx < tot) {
        int e = idx * 4;
        int which = e / (CDIM * CDIM);
        int off = e - which * (CDIM * CDIM);
        const float* src = which == 0 ? qw : which == 1 ? kw : vw;
        *(float4*)(w + e) = *(const float4*)(src + off);
    }
    if (idx < 3 * CDIM) {
        int which = idx / CDIM, off = idx % CDIM;
        bias[idx] = (which == 0 ? qb : which == 1 ? kb : vb)[off];
    }
}

// ---------------- im2col patch gather (float4) ----------------
__global__ void gather_k(const float* __restrict__ smri, float* __restrict__ pat) {
    int idx = blockIdx.x * 256 + threadIdx.x;
    if (idx >= BQ * NPATCH * 512 / 4) return;
    int e  = idx * 4;
    int kk = e & 511;
    int m  = e >> 9;
    int bb = m / NPATCH, p = m % NPATCH;
    int gx = p / (GD * GD), gy = (p / GD) % GD, gz = p % GD;
    int i = kk >> 6, j = (kk >> 3) & 7, kq = kk & 7;
    const float* src = smri + (((size_t)bb * IMG + gx * PSZ + i) * IMG + gy * PSZ + j) * IMG
                       + gz * PSZ + kq;
    *(float4*)(pat + e) = *(const float4*)src;
}

// ---------------- LN(patch embed) + cls + pos_embed ----------------
__global__ void ln_pos_k(const float* __restrict__ tmp, const float* __restrict__ g,
                         const float* __restrict__ b, const float* __restrict__ cls,
                         const float* __restrict__ pos, float* __restrict__ x)
{
    int bt = blockIdx.x;
    int bb = bt / NTOK, t = bt % NTOK;
    int tid = threadIdx.x;
    float* out = x + (size_t)bt * CDIM;
    const float* pp = pos + (size_t)t * CDIM;
    if (t == 0) {
        for (int c = tid; c < CDIM; c += 256) out[c] = cls[c] + pp[c];
        return;
    }
    const float* row = tmp + ((size_t)bb * NPATCH + (t - 1)) * CDIM;
    __shared__ float red[256];
    float s = 0.f, s2 = 0.f;
    for (int c = tid; c < CDIM; c += 256) { float v = row[c]; s += v; s2 += v * v; }
    red[tid] = s; __syncthreads();
    for (int st = 128; st > 0; st >>= 1) { if (tid < st) red[tid] += red[tid + st]; __syncthreads(); }
    float mean = red[0] / CDIM; __syncthreads();
    red[tid] = s2; __syncthreads();
    for (int st = 128; st > 0; st >>= 1) { if (tid < st) red[tid] += red[tid + st]; __syncthreads(); }
    float var = red[0] / CDIM - mean * mean;
    float inv = rsqrtf(var + 1e-5f);
    for (int c = tid; c < CDIM; c += 256)
        out[c] = (row[c] - mean) * inv * g[c] + b[c] + pp[c];
}

// ---------------- row softmax; zero pad cols ----------------
__global__ void softmax_rows(float* __restrict__ S) {
    __shared__ float buf[NTOK];
    __shared__ float red[256];
    size_t row = blockIdx.x;
    float* p = S + row * (size_t)LDS_;
    int tid = threadIdx.x;
    float mx = -1e30f;
    for (int i = tid; i < NTOK; i += 256) { float v = p[i]; buf[i] = v; mx = fmaxf(mx, v); }
    red[tid] = mx; __syncthreads();
    for (int st = 128; st > 0; st >>= 1) { if (tid < st) red[tid] = fmaxf(red[tid], red[tid + st]); __syncthreads(); }
    mx = red[0]; __syncthreads();
    float sm = 0.f;
    for (int i = tid; i < NTOK; i += 256) { float e = __expf(buf[i] - mx); buf[i] = e; sm += e; }
    red[tid] = sm; __syncthreads();
    for (int st = 128; st > 0; st >>= 1) { if (tid < st) red[tid] += red[tid + st]; __syncthreads(); }
    float inv = 1.f / red[0];
    for (int i = tid; i < NTOK; i += 256) p[i] = buf[i] * inv;
    if (tid < LDS_ - NTOK) p[NTOK + tid] = 0.f;
}

// ---------------- CLS-query attention for a branch ----------------
__global__ void cls_attn_k(const float* __restrict__ q0, const float* __restrict__ kv,
                           float* __restrict__ oc)
{
    int z = blockIdx.x;
    int bb = z / NHEAD, hh = z % NHEAD;
    __shared__ float sS[NTOK];
    __shared__ float sq[HD];
    __shared__ float red[128];
    int tid = threadIdx.x;
    for (int j = tid; j < HD; j += 128) sq[j] = q0[bb * CDIM + hh * HD + j];
    __syncthreads();
    const float scale = 0.10206207261596577f;
    float mx = -1e30f;
    for (int t = tid; t < NTOK; t += 128) {
        const float* kr = kv + ((size_t)(bb * NTOK + t)) * (2 * CDIM) + hh * HD;
        float s = 0.f;
        for (int j = 0; j < HD; j++) s += sq[j] * kr[j];
        s *= scale;
        sS[t] = s;
        mx = fmaxf(mx, s);
    }
    red[tid] = mx; __syncthreads();
    for (int st = 64; st > 0; st >>= 1) { if (tid < st) red[tid] = fmaxf(red[tid], red[tid + st]); __syncthreads(); }
    mx = red[0]; __syncthreads();
    float sm = 0.f;
    for (int t = tid; t < NTOK; t += 128) { float e = __expf(sS[t] - mx); sS[t] = e; sm += e; }
    red[tid] = sm; __syncthreads();
    for (int st = 64; st > 0; st >>= 1) { if (tid < st) red[tid] += red[tid + st]; __syncthreads(); }
    float inv = 1.f / red[0];
    __syncthreads();
    if (tid < HD) {
        float acc = 0.f;
        for (int t = 0; t < NTOK; t++)
            acc += sS[t] * kv[((size_t)(bb * NTOK + t)) * (2 * CDIM) + CDIM + hh * HD + tid];
        oc[bb * CDIM + hh * HD + tid] = acc * inv;
    }
}

// ---------------- LN + head on CLS ----------------
__global__ void head_k(const float* __restrict__ fin, const float* __restrict__ g,
                       const float* __restrict__ b, const float* __restrict__ hw,
                       const float* __restrict__ hb, float* __restrict__ out)
{
    int bb = blockIdx.x;
    const float* row = fin + bb * CDIM;
    __shared__ float red[256];
    __shared__ float sn[CDIM];
    int tid = threadIdx.x;
    float s = 0.f, s2 = 0.f;
    for (int c = tid; c < CDIM; c += 256) { float v = row[c]; s += v; s2 += v * v; }
    red[tid] = s; __syncthreads();
    for (int st = 128; st > 0; st >>= 1) { if (tid < st) red[tid] += red[tid + st]; __syncthreads(); }
    float mean = red[0] / CDIM; __syncthreads();
    red[tid] = s2; __syncthreads();
    for (int st = 128; st > 0; st >>= 1) { if (tid < st) red[tid] += red[tid + st]; __syncthreads(); }
    float var = red[0] / CDIM - mean * mean;
    float inv = rsqrtf(var + 1e-5f);
    for (int c = tid; c < CDIM; c += 256) sn[c] = (row[c] - mean) * inv * g[c] + b[c];
    __syncthreads();
    if (tid < NCLS) {
        float acc = hb[tid];
        for (int c = 0; c < CDIM; c++) acc += sn[c] * hw[tid * CDIM + c];
        out[bb * NCLS + tid] = acc;
    }
}

// ---------------- host ----------------
static inline int cdiv(int a, int b) { return (a + b - 1) / b; }

static void gemm_nt(const float* A, const float* B, const float* bias, float* C,
                    int M, int Nn, int K, int lda, int ldb, int ldc,
                    size_t sAb = 0, size_t sAh = 0, size_t sBb = 0, size_t sBh = 0,
                    size_t sCb = 0, size_t sCh = 0, int nh = 1, int batches = 1,
                    float alphaC = 1.f, const float* alphaPtr = nullptr, int accum = 0)
{
    dim3 grid(cdiv(Nn, 128), cdiv(M, 128), batches);
    gemm_k<1><<<grid, 256>>>(A, B, bias, C, M, Nn, K, lda, ldb, ldc,
                             sAb, sAh, sBb, sBh, sCb, sCh, nh, alphaC, alphaPtr, accum);
}

static void gemm_nn(const float* A, const float* B, const float* bias, float* C,
                    int M, int Nn, int K, int lda, int ldb, int ldc,
                    size_t sAb, size_t sAh, size_t sBb, size_t sBh,
                    size_t sCb, size_t sCh, int nh, int batches)
{
    dim3 grid(cdiv(Nn, 128), cdiv(M, 128), batches);
    gemm_k<0><<<grid, 256>>>(A, B, bias, C, M, Nn, K, lda, ldb, ldc,
                             sAb, sAh, sBb, sBh, sCb, sCh, nh, 1.f, nullptr, 0);
}

extern "C" void kernel_launch(void* const* d_in, const int* in_sizes, int n_in,
                              void* d_out, int out_size)
{
    const float* smri     = (const float*)d_in[0];
    const float* conv_w   = (const float*)d_in[2];
    const float* conv_b   = (const float*)d_in[3];
    const float* pe_ln_g  = (const float*)d_in[4];
    const float* pe_ln_b  = (const float*)d_in[5];
    const float* q_w      = (const float*)d_in[6];
    const float* q_b      = (const float*)d_in[7];
    const float* k_w      = (const float*)d_in[8];
    const float* k_b      = (const float*)d_in[9];
    const float* v_w      = (const float*)d_in[10];
    const float* v_b      = (const float*)d_in[11];
    const float* loc_in_w = (const float*)d_in[13];
    const float* loc_in_b = (const float*)d_in[14];
    const float* loc_out_w= (const float*)d_in[15];
    const float* loc_out_b= (const float*)d_in[16];
    const float* glob_in_w = (const float*)d_in[17];
    const float* glob_in_b = (const float*)d_in[18];
    const float* glob_out_w= (const float*)d_in[19];
    const float* glob_out_b= (const float*)d_in[20];
    const float* w_local  = (const float*)d_in[21];
    const float* w_global = (const float*)d_in[22];
    const float* cls_tok  = (const float*)d_in[23];
    const float* pos_emb  = (const float*)d_in[24];
    const float* head_ln_g= (const float*)d_in[25];
    const float* head_ln_b= (const float*)d_in[26];
    const float* head_w   = (const float*)d_in[27];
    const float* head_b   = (const float*)d_in[28];
    float* out = (float*)d_out;

    float *pat, *tmp, *x, *wqkv, *bqkv, *qkv, *S, *x2, *kv, *q0, *oc, *fin;
    cudaGetSymbolAddress((void**)&pat,  g_pat);
    cudaGetSymbolAddress((void**)&tmp,  g_tmp);
    cudaGetSymbolAddress((void**)&x,    g_x);
    cudaGetSymbolAddress((void**)&wqkv, g_wqkv);
    cudaGetSymbolAddress((void**)&bqkv, g_bqkv);
    cudaGetSymbolAddress((void**)&qkv,  g_qkv);
    cudaGetSymbolAddress((void**)&S,    g_S);
    cudaGetSymbolAddress((void**)&x2,   g_x2);
    cudaGetSymbolAddress((void**)&kv,   g_kv);
    cudaGetSymbolAddress((void**)&q0,   g_q0);
    cudaGetSymbolAddress((void**)&oc,   g_oc);
    cudaGetSymbolAddress((void**)&fin,  g_fin);

    const float scale = 0.10206207261596577f;   // 1/sqrt(96)
    const size_t sT  = (size_t)NTOK * CDIM;
    const size_t sT3 = (size_t)NTOK * 3 * CDIM;
    const size_t sSh = (size_t)NTOK * LDS_;
    const size_t sSb = (size_t)NHEAD * sSh;

    // 0) pack QKV weights
    pack_qkv_k<<<cdiv(3 * CDIM * CDIM / 4, 256), 256>>>(q_w, k_w, v_w, q_b, k_b, v_b,
                                                        wqkv, bqkv);

    // 1) patch im2col + embed GEMM
    gather_k<<<cdiv(BQ * NPATCH * 512 / 4, 256), 256>>>(smri, pat);
    gemm_nt(pat, conv_w, conv_b, tmp, BQ * NPATCH, CDIM, 512, 512, 512, CDIM);

    // 2) LN + cls + pos
    ln_pos_k<<<BQ * NTOK, 256>>>(tmp, pe_ln_g, pe_ln_b, cls_tok, pos_emb, x);

    // 3) fused QKV projection
    gemm_nt(x, wqkv, bqkv, qkv, BQ * NTOK, 3 * CDIM, CDIM, CDIM, CDIM, 3 * CDIM);

    // 4) scores = scale * Q K^T   (region bias is softmax-invariant -> dropped)
    gemm_nt(qkv, qkv + CDIM, nullptr, S, NTOK, NTOK, HD, 3 * CDIM, 3 * CDIM, LDS_,
            sT3, HD, sT3, HD, sSb, sSh, NHEAD, BQ * NHEAD, scale);

    // 5) softmax rows (+ zero pad cols)
    softmax_rows<<<BQ * NHEAD * NTOK, 256>>>(S);

    // 6) x2 = A @ V
    gemm_nn(S, qkv + 2 * CDIM, nullptr, x2, NTOK, HD, LDS_, LDS_, 3 * CDIM, CDIM,
            sSb, sSh, sT3, HD, sT, HD, NHEAD, BQ * NHEAD);

    // 7) branches (only CLS row used downstream)
    gemm_nt(x2, loc_in_w + (size_t)CDIM * CDIM, loc_in_b + CDIM, kv,
            BQ * NTOK, 2 * CDIM, CDIM, CDIM, CDIM, 2 * CDIM);
    gemm_nt(x2, loc_in_w, loc_in_b, q0, BQ, CDIM, CDIM, (int)sT, CDIM, CDIM);
    cls_attn_k<<<BQ * NHEAD, 128>>>(q0, kv, oc);
    gemm_nt(oc, loc_out_w, loc_out_b, fin, BQ, CDIM, CDIM, CDIM, CDIM, CDIM,
            0, 0, 0, 0, 0, 0, 1, 1, 1.f, w_local, 0);
    gemm_nt(x2, glob_in_w + (size_t)CDIM * CDIM, glob_in_b + CDIM, kv,
            BQ * NTOK, 2 * CDIM, CDIM, CDIM, CDIM, 2 * CDIM);
    gemm_nt(x2, glob_in_w, glob_in_b, q0, BQ, CDIM, CDIM, (int)sT, CDIM, CDIM);
    cls_attn_k<<<BQ * NHEAD, 128>>>(q0, kv, oc);
    gemm_nt(oc, glob_out_w, glob_out_b, fin, BQ, CDIM, CDIM, CDIM, CDIM, CDIM,
            0, 0, 0, 0, 0, 0, 1, 1, 1.f, w_global, 1);

    // 8) head on CLS
    head_k<<<BQ, 256>>>(fin, head_ln_g, head_ln_b, head_w, head_b, out);
}

// round 8
// speedup vs baseline: 2.2691x; 1.6343x over previous
#include <cuda_runtime.h>
#include <math.h>

#define IMG 96
#define PSZ 8
#define GD 12
#define CDIM 768
#define NHEAD 8
#define HD 96
#define NPATCH 1728
#define NTOK 1729
#define LDS_ 1744            // padded score ld: multiple of 16
#define BQ 2
#define NCLS 3

// ---------------- scratch (device globals) ----------------
__device__ float g_pat [(size_t)BQ * NPATCH * 512];
__device__ float g_tmp [(size_t)BQ * NPATCH * CDIM];
__device__ float g_x   [(size_t)BQ * NTOK * CDIM];
__device__ float g_wqkv[(size_t)3 * CDIM * CDIM];
__device__ float g_bqkv[3 * CDIM];
__device__ float g_qkv [(size_t)BQ * NTOK * 3 * CDIM];
__device__ float g_S   [(size_t)BQ * NHEAD * NTOK * LDS_];
__device__ float g_x2  [(size_t)BQ * NTOK * CDIM];
__device__ float g_kv  [(size_t)BQ * NTOK * 2 * CDIM];
__device__ float g_q0  [BQ * CDIM];
__device__ float g_oc  [BQ * CDIM];
__device__ float g_fin [BQ * CDIM];

__device__ __forceinline__ float to_tf32(float x) {
    unsigned u;
    asm("cvt.rna.tf32.f32 %0, %1;" : "=r"(u) : "f"(x));
    return __uint_as_float(u);
}

__device__ __forceinline__ float4 ld4_guard(const float* __restrict__ p, int gk, int K) {
    if (gk + 3 < K) return *(const float4*)(p + gk);
    float4 v = make_float4(0.f, 0.f, 0.f, 0.f);
    if (gk     < K) v.x = p[gk];
    if (gk + 1 < K) v.y = p[gk + 1];
    if (gk + 2 < K) v.z = p[gk + 2];
    return v;
}

// ---- 128x128x16 double-buffered GEMM on tf32 mma.sync (m16n8k8), fp32 accum ----
// TRANS_B=1: C[m,n] = sum_k A[m,k]*B[n,k]   TRANS_B=0: C[m,n] = sum_k A[m,k]*B[k,n]
template <int TRANS_B>
__global__ void __launch_bounds__(256, 2)
gemm_k(const float* __restrict__ A, const float* __restrict__ Bm,
       const float* __restrict__ bias, float* __restrict__ Cm,
       int M, int Nn, int K, int lda, int ldb, int ldc,
       size_t sAb, size_t sAh, size_t sBb, size_t sBh,
       size_t sCb, size_t sCh, int nh,
       float alphaC, const float* __restrict__ alphaPtr, int accum)
{
    int z = blockIdx.z;
    int bb = z / nh, hh = z % nh;
    A  += (size_t)bb * sAb + (size_t)hh * sAh;
    Bm += (size_t)bb * sBb + (size_t)hh * sBh;
    Cm += (size_t)bb * sCb + (size_t)hh * sCh;

    // [buf][k][idx]; stride 136 -> frag LDS bank-conflict-free (136 mod 32 = 8)
    __shared__ __align__(16) float As[2][16][136];
    __shared__ __align__(16) float Bs[2][16][136];

    int tid = threadIdx.x;
    int m0 = blockIdx.y * 128, n0 = blockIdx.x * 128;

    // loaders
    int ar = tid >> 2;            // 0..63
    int ak = (tid & 3) * 4;       // 0,4,8,12
    int bk = tid >> 5;            // 0..7  (NN loader)
    int bc = (tid & 31) * 4;      // 0..124

    // mma geometry: 8 warps -> 2x4 warp grid, warp tile 64x32
    int wid = tid >> 5, lane = tid & 31;
    int wm = (wid & 1) * 64, wn = (wid >> 1) * 32;
    int grp = lane >> 2, qid = lane & 3;

    float acc[4][4][4];
#pragma unroll
    for (int i = 0; i < 4; i++)
#pragma unroll
        for (int j = 0; j < 4; j++)
#pragma unroll
            for (int r = 0; r < 4; r++) acc[i][j][r] = 0.f;

    float4 pa[2], pb[2];
    int ktiles = (K + 15) / 16;

    // ---- prologue: load tile 0 ----
    {
        int k0 = 0;
#pragma unroll
        for (int h = 0; h < 2; h++) {
            int gm = m0 + ar + h * 64;
            pa[h] = (gm < M) ? ld4_guard(A + (size_t)gm * lda, k0 + ak, K)
                             : make_float4(0.f, 0.f, 0.f, 0.f);
        }
        if (TRANS_B) {
#pragma unroll
            for (int h = 0; h < 2; h++) {
                int gn = n0 + ar + h * 64;
                pb[h] = (gn < Nn) ? ld4_guard(Bm + (size_t)gn * ldb, k0 + ak, K)
                                  : make_float4(0.f, 0.f, 0.f, 0.f);
            }
        } else {
#pragma unroll
            for (int h = 0; h < 2; h++) {
                int gk = k0 + bk + h * 8;
                int gn = n0 + bc;
                float4 v = make_float4(0.f, 0.f, 0.f, 0.f);
                if (gk < K) {
                    const float* rp = Bm + (size_t)gk * ldb;
                    if (gn + 3 < Nn) v = *(const float4*)(rp + gn);
                    else {
                        if (gn     < Nn) v.x = rp[gn];
                        if (gn + 1 < Nn) v.y = rp[gn + 1];
                        if (gn + 2 < Nn) v.z = rp[gn + 2];
                    }
                }
                pb[h] = v;
            }
        }
#pragma unroll
        for (int h = 0; h < 2; h++) {
            int r = ar + h * 64;
            As[0][ak + 0][r] = to_tf32(pa[h].x); As[0][ak + 1][r] = to_tf32(pa[h].y);
            As[0][ak + 2][r] = to_tf32(pa[h].z); As[0][ak + 3][r] = to_tf32(pa[h].w);
        }
        if (TRANS_B) {
#pragma unroll
            for (int h = 0; h < 2; h++) {
                int r = ar + h * 64;
                Bs[0][ak + 0][r] = to_tf32(pb[h].x); Bs[0][ak + 1][r] = to_tf32(pb[h].y);
                Bs[0][ak + 2][r] = to_tf32(pb[h].z); Bs[0][ak + 3][r] = to_tf32(pb[h].w);
            }
        } else {
#pragma unroll
            for (int h = 0; h < 2; h++) {
                float4 v = pb[h];
                v.x = to_tf32(v.x); v.y = to_tf32(v.y);
                v.z = to_tf32(v.z); v.w = to_tf32(v.w);
                *(float4*)&Bs[0][bk + h * 8][bc] = v;
            }
        }
    }
    __syncthreads();

    for (int t = 0; t < ktiles; t++) {
        int cur = t & 1;
        // ---- prefetch tile t+1 ----
        if (t + 1 < ktiles) {
            int k0 = (t + 1) * 16;
#pragma unroll
            for (int h = 0; h < 2; h++) {
                int gm = m0 + ar + h * 64;
                pa[h] = (gm < M) ? ld4_guard(A + (size_t)gm * lda, k0 + ak, K)
                                 : make_float4(0.f, 0.f, 0.f, 0.f);
            }
            if (TRANS_B) {
#pragma unroll
                for (int h = 0; h < 2; h++) {
                    int gn = n0 + ar + h * 64;
                    pb[h] = (gn < Nn) ? ld4_guard(Bm + (size_t)gn * ldb, k0 + ak, K)
                                      : make_float4(0.f, 0.f, 0.f, 0.f);
                }
            } else {
#pragma unroll
                for (int h = 0; h < 2; h++) {
                    int gk = k0 + bk + h * 8;
                    int gn = n0 + bc;
                    float4 v = make_float4(0.f, 0.f, 0.f, 0.f);
                    if (gk < K) {
                        const float* rp = Bm + (size_t)gk * ldb;
                        if (gn + 3 < Nn) v = *(const float4*)(rp + gn);
                        else {
                            if (gn     < Nn) v.x = rp[gn];
                            if (gn + 1 < Nn) v.y = rp[gn + 1];
                            if (gn + 2 < Nn) v.z = rp[gn + 2];
                        }
                    }
                    pb[h] = v;
                }
            }
        }

        // ---- compute tile t: 2 k-steps of mma.m16n8k8.tf32 ----
#pragma unroll
        for (int ks = 0; ks < 2; ks++) {
            int kb = ks * 8;
            unsigned a[4][4], b[4][2];
#pragma unroll
            for (int i = 0; i < 4; i++) {
                int rm = wm + i * 16 + grp;
                a[i][0] = __float_as_uint(As[cur][kb + qid][rm]);
                a[i][1] = __float_as_uint(As[cur][kb + qid][rm + 8]);
                a[i][2] = __float_as_uint(As[cur][kb + qid + 4][rm]);
                a[i][3] = __float_as_uint(As[cur][kb + qid + 4][rm + 8]);
            }
#pragma unroll
            for (int j = 0; j < 4; j++) {
                int cn = wn + j * 8 + grp;
                b[j][0] = __float_as_uint(Bs[cur][kb + qid][cn]);
                b[j][1] = __float_as_uint(Bs[cur][kb + qid + 4][cn]);
            }
#pragma unroll
            for (int i = 0; i < 4; i++)
#pragma unroll
                for (int j = 0; j < 4; j++)
                    asm("mma.sync.aligned.m16n8k8.row.col.f32.tf32.tf32.f32 "
                        "{%0,%1,%2,%3}, {%4,%5,%6,%7}, {%8,%9}, {%0,%1,%2,%3};"
                        : "+f"(acc[i][j][0]), "+f"(acc[i][j][1]),
                          "+f"(acc[i][j][2]), "+f"(acc[i][j][3])
                        : "r"(a[i][0]), "r"(a[i][1]), "r"(a[i][2]), "r"(a[i][3]),
                          "r"(b[j][0]), "r"(b[j][1]));
        }

        // ---- store prefetched regs into other buffer ----
        if (t + 1 < ktiles) {
            int nxt = cur ^ 1;
#pragma unroll
            for (int h = 0; h < 2; h++) {
                int r = ar + h * 64;
                As[nxt][ak + 0][r] = to_tf32(pa[h].x); As[nxt][ak + 1][r] = to_tf32(pa[h].y);
                As[nxt][ak + 2][r] = to_tf32(pa[h].z); As[nxt][ak + 3][r] = to_tf32(pa[h].w);
            }
            if (TRANS_B) {
#pragma unroll
                for (int h = 0; h < 2; h++) {
                    int r = ar + h * 64;
                    Bs[nxt][ak + 0][r] = to_tf32(pb[h].x); Bs[nxt][ak + 1][r] = to_tf32(pb[h].y);
                    Bs[nxt][ak + 2][r] = to_tf32(pb[h].z); Bs[nxt][ak + 3][r] = to_tf32(pb[h].w);
                }
            } else {
#pragma unroll
                for (int h = 0; h < 2; h++) {
                    float4 v = pb[h];
                    v.x = to_tf32(v.x); v.y = to_tf32(v.y);
                    v.z = to_tf32(v.z); v.w = to_tf32(v.w);
                    *(float4*)&Bs[nxt][bk + h * 8][bc] = v;
                }
            }
            __syncthreads();
        }
    }

    // ---- epilogue ----
    float alpha = alphaC * (alphaPtr ? *alphaPtr : 1.f);
#pragma unroll
    for (int i = 0; i < 4; i++) {
#pragma unroll
        for (int j = 0; j < 4; j++) {
            int c0 = n0 + wn + j * 8 + qid * 2;
#pragma unroll
            for (int h = 0; h < 2; h++) {
                int r = m0 + wm + i * 16 + grp + h * 8;
                if (r >= M) continue;
                float v0 = acc[i][j][h * 2], v1 = acc[i][j][h * 2 + 1];
                if (bias) {
                    if (c0     < Nn) v0 += bias[c0];
                    if (c0 + 1 < Nn) v1 += bias[c0 + 1];
                }
                v0 *= alpha; v1 *= alpha;
                size_t off = (size_t)r * ldc + c0;
                if (c0 + 1 < Nn && ((ldc & 1) == 0)) {
                    if (accum) { v0 += Cm[off]; v1 += Cm[off + 1]; }
                    *(float2*)(Cm + off) = make_float2(v0, v1);
                } else {
                    if (c0 < Nn) {
                        if (accum) v0 += Cm[off];
                        Cm[off] = v0;
                    }
                    if (c0 + 1 < Nn) {
                        if (accum) v1 += Cm[off + 1];
                        Cm[off + 1] = v1;
                    }
                }
            }
        }
    }
}

// ---------------- pack QKV weights/bias into one matrix ----------------
__global__ void pack_qkv_k(const float* __restrict__ qw, const float* __restrict__ kw,
                           const float* __restrict__ vw, const float* __restrict__ qb,
                           const float* __restrict__ kb, const float* __restrict__ vb,
                           float* __restrict__ w, float* __restrict__ bias)
{
    int idx = blockIdx.x * 256 + threadIdx.x;
    int tot = 3 * CDIM * CDIM / 4;
    if (idx < tot) {
        int e = idx * 4;
        int which = e / (CDIM * CDIM);
        int off = e - which * (CDIM * CDIM);
        const float* src = which == 0 ? qw : which == 1 ? kw : vw;
        *(float4*)(w + e) = *(const float4*)(src + off);
    }
    if (idx < 3 * CDIM) {
        int which = idx / CDIM, off = idx % CDIM;
        bias[idx] = (which == 0 ? qb : which == 1 ? kb : vb)[off];
    }
}

// ---------------- im2col patch gather (float4) ----------------
__global__ void gather_k(const float* __restrict__ smri, float* __restrict__ pat) {
    int idx = blockIdx.x * 256 + threadIdx.x;
    if (idx >= BQ * NPATCH * 512 / 4) return;
    int e  = idx * 4;
    int kk = e & 511;
    int m  = e >> 9;
    int bb = m / NPATCH, p = m % NPATCH;
    int gx = p / (GD * GD), gy = (p / GD) % GD, gz = p % GD;
    int i = kk >> 6, j = (kk >> 3) & 7, kq = kk & 7;
    const float* src = smri + (((size_t)bb * IMG + gx * PSZ + i) * IMG + gy * PSZ + j) * IMG
                       + gz * PSZ + kq;
    *(float4*)(pat + e) = *(const float4*)src;
}

// ---------------- LN(patch embed) + cls + pos_embed ----------------
__global__ void ln_pos_k(const float* __restrict__ tmp, const float* __restrict__ g,
                         const float* __restrict__ b, const float* __restrict__ cls,
                         const float* __restrict__ pos, float* __restrict__ x)
{
    int bt = blockIdx.x;
    int bb = bt / NTOK, t = bt % NTOK;
    int tid = threadIdx.x;
    float* out = x + (size_t)bt * CDIM;
    const float* pp = pos + (size_t)t * CDIM;
    if (t == 0) {
        for (int c = tid; c < CDIM; c += 256) out[c] = cls[c] + pp[c];
        return;
    }
    const float* row = tmp + ((size_t)bb * NPATCH + (t - 1)) * CDIM;
    __shared__ float red[256];
    float s = 0.f, s2 = 0.f;
    for (int c = tid; c < CDIM; c += 256) { float v = row[c]; s += v; s2 += v * v; }
    red[tid] = s; __syncthreads();
    for (int st = 128; st > 0; st >>= 1) { if (tid < st) red[tid] += red[tid + st]; __syncthreads(); }
    float mean = red[0] / CDIM; __syncthreads();
    red[tid] = s2; __syncthreads();
    for (int st = 128; st > 0; st >>= 1) { if (tid < st) red[tid] += red[tid + st]; __syncthreads(); }
    float var = red[0] / CDIM - mean * mean;
    float inv = rsqrtf(var + 1e-5f);
    for (int c = tid; c < CDIM; c += 256)
        out[c] = (row[c] - mean) * inv * g[c] + b[c] + pp[c];
}

// ---------------- vectorized row softmax (float4 + shuffle reductions) ----------
__global__ void softmax_rows(float* __restrict__ S) {
    __shared__ __align__(16) float buf[LDS_];
    __shared__ float red[8];
    size_t row = blockIdx.x;
    float* p = S + row * (size_t)LDS_;
    int tid = threadIdx.x, lane = tid & 31, wrp = tid >> 5;
    const int NV4 = LDS_ / 4;  // 436

    float mx = -1e30f;
    for (int i = tid; i < NV4; i += 256) {
        float4 v = ((const float4*)p)[i];
        int e = i * 4;
        v.x = (e + 0 < NTOK) ? v.x : -1e30f;
        v.y = (e + 1 < NTOK) ? v.y : -1e30f;
        v.z = (e + 2 < NTOK) ? v.z : -1e30f;
        v.w = (e + 3 < NTOK) ? v.w : -1e30f;
        ((float4*)buf)[i] = v;
        mx = fmaxf(mx, fmaxf(fmaxf(v.x, v.y), fmaxf(v.z, v.w)));
    }
#pragma unroll
    for (int o = 16; o; o >>= 1) mx = fmaxf(mx, __shfl_xor_sync(0xffffffffu, mx, o));
    if (lane == 0) red[wrp] = mx;
    __syncthreads();
    if (tid == 0) {
        float m = red[0];
#pragma unroll
        for (int i = 1; i < 8; i++) m = fmaxf(m, red[i]);
        red[0] = m;
    }
    __syncthreads();
    mx = red[0];

    float sm = 0.f;
    for (int i = tid; i < NV4; i += 256) {
        float4 v = ((float4*)buf)[i];
        v.x = __expf(v.x - mx); v.y = __expf(v.y - mx);
        v.z = __expf(v.z - mx); v.w = __expf(v.w - mx);
        ((float4*)buf)[i] = v;
        sm += v.x + v.y + v.z + v.w;
    }
#pragma unroll
    for (int o = 16; o; o >>= 1) sm += __shfl_xor_sync(0xffffffffu, sm, o);
    if (lane == 0) red[wrp] = sm;
    __syncthreads();
    if (tid == 0) {
        float m = 0.f;
#pragma unroll
        for (int i = 0; i < 8; i++) m += red[i];
        red[0] = m;
    }
    __syncthreads();
    float inv = 1.f / red[0];

    for (int i = tid; i < NV4; i += 256) {
        float4 v = ((float4*)buf)[i];
        v.x *= inv; v.y *= inv; v.z *= inv; v.w *= inv;
        ((float4*)p)[i] = v;
    }
}

// ---------------- CLS-query attention for a branch ----------------
__global__ void cls_attn_k(const float* __restrict__ q0, const float* __restrict__ kv,
                           float* __restrict__ oc)
{
    int z = blockIdx.x;
    int bb = z / NHEAD, hh = z % NHEAD;
    __shared__ float sS[NTOK];
    __shared__ float sq[HD];
    __shared__ float red[128];
    int tid = threadIdx.x;
    for (int j = tid; j < HD; j += 128) sq[j] = q0[bb * CDIM + hh * HD + j];
    __syncthreads();
    const float scale = 0.10206207261596577f;
    float mx = -1e30f;
    for (int t = tid; t < NTOK; t += 128) {
        const float* kr = kv + ((size_t)(bb * NTOK + t)) * (2 * CDIM) + hh * HD;
        float s = 0.f;
        for (int j = 0; j < HD; j++) s += sq[j] * kr[j];
        s *= scale;
        sS[t] = s;
        mx = fmaxf(mx, s);
    }
    red[tid] = mx; __syncthreads();
    for (int st = 64; st > 0; st >>= 1) { if (tid < st) red[tid] = fmaxf(red[tid], red[tid + st]); __syncthreads(); }
    mx = red[0]; __syncthreads();
    float sm = 0.f;
    for (int t = tid; t < NTOK; t += 128) { float e = __expf(sS[t] - mx); sS[t] = e; sm += e; }
    red[tid] = sm; __syncthreads();
    for (int st = 64; st > 0; st >>= 1) { if (tid < st) red[tid] += red[tid + st]; __syncthreads(); }
    float inv = 1.f / red[0];
    __syncthreads();
    if (tid < HD) {
        float acc = 0.f;
        for (int t = 0; t < NTOK; t++)
            acc += sS[t] * kv[((size_t)(bb * NTOK + t)) * (2 * CDIM) + CDIM + hh * HD + tid];
        oc[bb * CDIM + hh * HD + tid] = acc * inv;
    }
}

// ---------------- LN + head on CLS ----------------
__global__ void head_k(const float* __restrict__ fin, const float* __restrict__ g,
                       const float* __restrict__ b, const float* __restrict__ hw,
                       const float* __restrict__ hb, float* __restrict__ out)
{
    int bb = blockIdx.x;
    const float* row = fin + bb * CDIM;
    __shared__ float red[256];
    __shared__ float sn[CDIM];
    int tid = threadIdx.x;
    float s = 0.f, s2 = 0.f;
    for (int c = tid; c < CDIM; c += 256) { float v = row[c]; s += v; s2 += v * v; }
    red[tid] = s; __syncthreads();
    for (int st = 128; st > 0; st >>= 1) { if (tid < st) red[tid] += red[tid + st]; __syncthreads(); }
    float mean = red[0] / CDIM; __syncthreads();
    red[tid] = s2; __syncthreads();
    for (int st = 128; st > 0; st >>= 1) { if (tid < st) red[tid] += red[tid + st]; __syncthreads(); }
    float var = red[0] / CDIM - mean * mean;
    float inv = rsqrtf(var + 1e-5f);
    for (int c = tid; c < CDIM; c += 256) sn[c] = (row[c] - mean) * inv * g[c] + b[c];
    __syncthreads();
    if (tid < NCLS) {
        float acc = hb[tid];
        for (int c = 0; c < CDIM; c++) acc += sn[c] * hw[tid * CDIM + c];
        out[bb * NCLS + tid] = acc;
    }
}

// ---------------- host ----------------
static inline int cdiv(int a, int b) { return (a + b - 1) / b; }

static void gemm_nt(const float* A, const float* B, const float* bias, float* C,
                    int M, int Nn, int K, int lda, int ldb, int ldc,
                    size_t sAb = 0, size_t sAh = 0, size_t sBb = 0, size_t sBh = 0,
                    size_t sCb = 0, size_t sCh = 0, int nh = 1, int batches = 1,
                    float alphaC = 1.f, const float* alphaPtr = nullptr, int accum = 0)
{
    dim3 grid(cdiv(Nn, 128), cdiv(M, 128), batches);
    gemm_k<1><<<grid, 256>>>(A, B, bias, C, M, Nn, K, lda, ldb, ldc,
                             sAb, sAh, sBb, sBh, sCb, sCh, nh, alphaC, alphaPtr, accum);
}

static void gemm_nn(const float* A, const float* B, const float* bias, float* C,
                    int M, int Nn, int K, int lda, int ldb, int ldc,
                    size_t sAb, size_t sAh, size_t sBb, size_t sBh,
                    size_t sCb, size_t sCh, int nh, int batches)
{
    dim3 grid(cdiv(Nn, 128), cdiv(M, 128), batches);
    gemm_k<0><<<grid, 256>>>(A, B, bias, C, M, Nn, K, lda, ldb, ldc,
                             sAb, sAh, sBb, sBh, sCb, sCh, nh, 1.f, nullptr, 0);
}

extern "C" void kernel_launch(void* const* d_in, const int* in_sizes, int n_in,
                              void* d_out, int out_size)
{
    const float* smri     = (const float*)d_in[0];
    const float* conv_w   = (const float*)d_in[2];
    const float* conv_b   = (const float*)d_in[3];
    const float* pe_ln_g  = (const float*)d_in[4];
    const float* pe_ln_b  = (const float*)d_in[5];
    const float* q_w      = (const float*)d_in[6];
    const float* q_b      = (const float*)d_in[7];
    const float* k_w      = (const float*)d_in[8];
    const float* k_b      = (const float*)d_in[9];
    const float* v_w      = (const float*)d_in[10];
    const float* v_b      = (const float*)d_in[11];
    const float* loc_in_w = (const float*)d_in[13];
    const float* loc_in_b = (const float*)d_in[14];
    const float* loc_out_w= (const float*)d_in[15];
    const float* loc_out_b= (const float*)d_in[16];
    const float* glob_in_w = (const float*)d_in[17];
    const float* glob_in_b = (const float*)d_in[18];
    const float* glob_out_w= (const float*)d_in[19];
    const float* glob_out_b= (const float*)d_in[20];
    const float* w_local  = (const float*)d_in[21];
    const float* w_global = (const float*)d_in[22];
    const float* cls_tok  = (const float*)d_in[23];
    const float* pos_emb  = (const float*)d_in[24];
    const float* head_ln_g= (const float*)d_in[25];
    const float* head_ln_b= (const float*)d_in[26];
    const float* head_w   = (const float*)d_in[27];
    const float* head_b   = (const float*)d_in[28];
    float* out = (float*)d_out;

    float *pat, *tmp, *x, *wqkv, *bqkv, *qkv, *S, *x2, *kv, *q0, *oc, *fin;
    cudaGetSymbolAddress((void**)&pat,  g_pat);
    cudaGetSymbolAddress((void**)&tmp,  g_tmp);
    cudaGetSymbolAddress((void**)&x,    g_x);
    cudaGetSymbolAddress((void**)&wqkv, g_wqkv);
    cudaGetSymbolAddress((void**)&bqkv, g_bqkv);
    cudaGetSymbolAddress((void**)&qkv,  g_qkv);
    cudaGetSymbolAddress((void**)&S,    g_S);
    cudaGetSymbolAddress((void**)&x2,   g_x2);
    cudaGetSymbolAddress((void**)&kv,   g_kv);
    cudaGetSymbolAddress((void**)&q0,   g_q0);
    cudaGetSymbolAddress((void**)&oc,   g_oc);
    cudaGetSymbolAddress((void**)&fin,  g_fin);

    const float scale = 0.10206207261596577f;   // 1/sqrt(96)
    const size_t sT  = (size_t)NTOK * CDIM;
    const size_t sT3 = (size_t)NTOK * 3 * CDIM;
    const size_t sSh = (size_t)NTOK * LDS_;
    const size_t sSb = (size_t)NHEAD * sSh;

    // 0) pack QKV weights
    pack_qkv_k<<<cdiv(3 * CDIM * CDIM / 4, 256), 256>>>(q_w, k_w, v_w, q_b, k_b, v_b,
                                                        wqkv, bqkv);

    // 1) patch im2col + embed GEMM
    gather_k<<<cdiv(BQ * NPATCH * 512 / 4, 256), 256>>>(smri, pat);
    gemm_nt(pat, conv_w, conv_b, tmp, BQ * NPATCH, CDIM, 512, 512, 512, CDIM);

    // 2) LN + cls + pos
    ln_pos_k<<<BQ * NTOK, 256>>>(tmp, pe_ln_g, pe_ln_b, cls_tok, pos_emb, x);

    // 3) fused QKV projection
    gemm_nt(x, wqkv, bqkv, qkv, BQ * NTOK, 3 * CDIM, CDIM, CDIM, CDIM, 3 * CDIM);

    // 4) scores = scale * Q K^T   (region bias is softmax-invariant -> dropped)
    gemm_nt(qkv, qkv + CDIM, nullptr, S, NTOK, NTOK, HD, 3 * CDIM, 3 * CDIM, LDS_,
            sT3, HD, sT3, HD, sSb, sSh, NHEAD, BQ * NHEAD, scale);

    // 5) softmax rows (+ zero pad cols)
    softmax_rows<<<BQ * NHEAD * NTOK, 256>>>(S);

    // 6) x2 = A @ V
    gemm_nn(S, qkv + 2 * CDIM, nullptr, x2, NTOK, HD, LDS_, LDS_, 3 * CDIM, CDIM,
            sSb, sSh, sT3, HD, sT, HD, NHEAD, BQ * NHEAD);

    // 7) branches (only CLS row used downstream)
    gemm_nt(x2, loc_in_w + (size_t)CDIM * CDIM, loc_in_b + CDIM, kv,
            BQ * NTOK, 2 * CDIM, CDIM, CDIM, CDIM, 2 * CDIM);
    gemm_nt(x2, loc_in_w, loc_in_b, q0, BQ, CDIM, CDIM, (int)sT, CDIM, CDIM);
    cls_attn_k<<<BQ * NHEAD, 128>>>(q0, kv, oc);
    gemm_nt(oc, loc_out_w, loc_out_b, fin, BQ, CDIM, CDIM, CDIM, CDIM, CDIM,
            0, 0, 0, 0, 0, 0, 1, 1, 1.f, w_local, 0);
    gemm_nt(x2, glob_in_w + (size_t)CDIM * CDIM, glob_in_b + CDIM, kv,
            BQ * NTOK, 2 * CDIM, CDIM, CDIM, CDIM, 2 * CDIM);
    gemm_nt(x2, glob_in_w, glob_in_b, q0, BQ, CDIM, CDIM, (int)sT, CDIM, CDIM);
    cls_attn_k<<<BQ * NHEAD, 128>>>(q0, kv, oc);
    gemm_nt(oc, glob_out_w, glob_out_b, fin, BQ, CDIM, CDIM, CDIM, CDIM, CDIM,
            0, 0, 0, 0, 0, 0, 1, 1, 1.f, w_global, 1);

    // 8) head on CLS
    head_k<<<BQ, 256>>>(fin, head_ln_g, head_ln_b, head_w, head_b, out);
}